// round 5
// baseline (speedup 1.0000x reference)
#include <cuda_runtime.h>

#define N_NODES 8192
#define NV4 (N_NODES / 4)       // 2048 float4 per row
#define PSI 64
#define THREADS_RS 512
#define GRID_RS 296             // 2 blocks per SM on 148 SMs
#define NCHUNK (N_NODES / 4)    // 2048 chunks of 4 rows
#define GRID_ES 128             // edge-scatter blocks (512 thr each)

// __device__ scratch (no allocations allowed). All zero-init at load;
// every replay restores them to zero (read-then-zero / self-reset tickets).
__device__ float g_agg[N_NODES];
__device__ float g_t[N_NODES];
__device__ float g_s[N_NODES];
__device__ unsigned int g_done1 = 0;
__device__ unsigned int g_done2 = 0;

// ---------------------------------------------------------------------------
// K1: edge MLP + scatter-add.  Last block to finish also runs the node MLP
// (g_agg -> g_t = struct^2) and re-zeros g_agg for the next replay.
// ---------------------------------------------------------------------------
__global__ __launch_bounds__(512) void k_edge_node(
        const int4* __restrict__ col4,
        const float4* __restrict__ val4,
        const float* __restrict__ w1e, const float* __restrict__ b1e,
        const float* __restrict__ w2e, const float* __restrict__ b2e,
        const float* __restrict__ w1n, const float* __restrict__ b1n,
        const float* __restrict__ w2n, const float* __restrict__ b2n,
        int nnz4) {
    __shared__ float sw1[PSI], sb1[PSI], sw2[PSI];
    __shared__ float sb2s;
    __shared__ bool s_last;

    const int tid = threadIdx.x;

    if (tid < PSI) {
        sw1[tid] = w1e[tid];
        sb1[tid] = b1e[tid];
        sw2[tid] = w2e[tid];
    }
    if (tid == 0) sb2s = b2e[0];
    __syncthreads();

    int i = blockIdx.x * 512 + tid;
    if (i < nnz4) {
        float4 v = val4[i];
        int4   c = col4[i];
        float a0 = sb2s, a1 = sb2s, a2 = sb2s, a3 = sb2s;
#pragma unroll
        for (int j = 0; j < PSI; j++) {
            float w = sw1[j], b = sb1[j], u = sw2[j];
            a0 = fmaf(fmaxf(fmaf(v.x, w, b), 0.0f), u, a0);
            a1 = fmaf(fmaxf(fmaf(v.y, w, b), 0.0f), u, a1);
            a2 = fmaf(fmaxf(fmaf(v.z, w, b), 0.0f), u, a2);
            a3 = fmaf(fmaxf(fmaf(v.w, w, b), 0.0f), u, a3);
        }
        atomicAdd(&g_agg[c.x], a0);
        atomicAdd(&g_agg[c.y], a1);
        atomicAdd(&g_agg[c.z], a2);
        atomicAdd(&g_agg[c.w], a3);
    }
    __syncthreads();

    // arrival ticket: last block runs the node MLP
    if (tid == 0) {
        __threadfence();
        unsigned int t = atomicAdd(&g_done1, 1u);
        s_last = (t == GRID_ES - 1u);
        if (s_last) g_done1 = 0;               // reset for next replay
    }
    __syncthreads();
    if (!s_last) return;

    __threadfence();                            // acquire all g_agg updates

    // node MLP weights
    if (tid < PSI) {
        sw1[tid] = w1n[tid];
        sb1[tid] = b1n[tid];
        sw2[tid] = w2n[tid];
    }
    if (tid == 0) sb2s = b2n[0];
    __syncthreads();

#pragma unroll
    for (int n = tid; n < N_NODES; n += 512) {
        float x = g_agg[n];
        g_agg[n] = 0.0f;                       // reset for next replay
        float acc = sb2s;
#pragma unroll
        for (int j = 0; j < PSI; j++) {
            float h = fmaf(x, sw1[j], sb1[j]);
            acc = fmaf(fmaxf(h, 0.0f), sw2[j], acc);
        }
        g_t[n] = acc * acc;
    }
}

// ---------------------------------------------------------------------------
// K2: persistent row score (identical hot loop to R3).  Last block to finish
// also performs the per-edge gather into out[].
// ---------------------------------------------------------------------------
__global__ __launch_bounds__(THREADS_RS, 2) void k_row_score(
        const float* __restrict__ adj,
        const int* __restrict__ src_nodes,
        float* __restrict__ out, int E) {
    __shared__ float st[N_NODES];              // 32 KB staged t
    __shared__ float warp_sum[16][4];
    __shared__ bool s_last;

    const int tid = threadIdx.x;

    // stage t once per block
    {
        const float4* tv = reinterpret_cast<const float4*>(g_t);
        float4* sv = reinterpret_cast<float4*>(st);
        for (int i = tid; i < NV4; i += THREADS_RS) sv[i] = tv[i];
    }
    __syncthreads();

    const float4* sv = reinterpret_cast<const float4*>(st);
    const int lane = tid & 31;
    const int wid  = tid >> 5;

    for (int c = blockIdx.x; c < NCHUNK; c += GRID_RS) {
        const int row0 = c * 4;
        const float4* a0 = reinterpret_cast<const float4*>(
            adj + (size_t)row0 * N_NODES);
        const float4* a1 = a0 + NV4;
        const float4* a2 = a1 + NV4;
        const float4* a3 = a2 + NV4;

        float s0 = 0.0f, s1 = 0.0f, s2 = 0.0f, s3 = 0.0f;
#pragma unroll
        for (int i = tid; i < NV4; i += THREADS_RS) {
            float4 v0 = __ldcs(&a0[i]);
            float4 v1 = __ldcs(&a1[i]);
            float4 v2 = __ldcs(&a2[i]);
            float4 v3 = __ldcs(&a3[i]);
            float4 tw = sv[i];
            s0 = fmaf(v0.x * v0.x, tw.x, s0);
            s0 = fmaf(v0.y * v0.y, tw.y, s0);
            s0 = fmaf(v0.z * v0.z, tw.z, s0);
            s0 = fmaf(v0.w * v0.w, tw.w, s0);
            s1 = fmaf(v1.x * v1.x, tw.x, s1);
            s1 = fmaf(v1.y * v1.y, tw.y, s1);
            s1 = fmaf(v1.z * v1.z, tw.z, s1);
            s1 = fmaf(v1.w * v1.w, tw.w, s1);
            s2 = fmaf(v2.x * v2.x, tw.x, s2);
            s2 = fmaf(v2.y * v2.y, tw.y, s2);
            s2 = fmaf(v2.z * v2.z, tw.z, s2);
            s2 = fmaf(v2.w * v2.w, tw.w, s2);
            s3 = fmaf(v3.x * v3.x, tw.x, s3);
            s3 = fmaf(v3.y * v3.y, tw.y, s3);
            s3 = fmaf(v3.z * v3.z, tw.z, s3);
            s3 = fmaf(v3.w * v3.w, tw.w, s3);
        }

#pragma unroll
        for (int off = 16; off > 0; off >>= 1) {
            s0 += __shfl_down_sync(0xffffffffu, s0, off);
            s1 += __shfl_down_sync(0xffffffffu, s1, off);
            s2 += __shfl_down_sync(0xffffffffu, s2, off);
            s3 += __shfl_down_sync(0xffffffffu, s3, off);
        }
        if (lane == 0) {
            warp_sum[wid][0] = s0;
            warp_sum[wid][1] = s1;
            warp_sum[wid][2] = s2;
            warp_sum[wid][3] = s3;
        }
        __syncthreads();
        if (tid < 64) {
            float v = warp_sum[tid & 15][tid >> 4];
            v += __shfl_down_sync(0xffffffffu, v, 8, 16);
            v += __shfl_down_sync(0xffffffffu, v, 4, 16);
            v += __shfl_down_sync(0xffffffffu, v, 2, 16);
            v += __shfl_down_sync(0xffffffffu, v, 1, 16);
            if ((tid & 15) == 0) g_s[row0 + (tid >> 4)] = v;
        }
        __syncthreads();
    }

    // arrival ticket: last block performs the gather
    if (tid == 0) {
        __threadfence();
        unsigned int t = atomicAdd(&g_done2, 1u);
        s_last = (t == GRID_RS - 1u);
        if (s_last) g_done2 = 0;               // reset for next replay
    }
    __syncthreads();
    if (!s_last) return;

    __threadfence();                            // acquire all g_s writes

    for (int e = tid; e < E; e += THREADS_RS)
        out[e] = g_s[src_nodes[e]];
}

// ---------------------------------------------------------------------------
// launch
// Inputs (metadata order): col, values, adj, src_nodes,
//                          w1e, b1e, w2e, b2e, w1n, b1n, w2n, b2n
// ---------------------------------------------------------------------------
extern "C" void kernel_launch(void* const* d_in, const int* in_sizes, int n_in,
                              void* d_out, int out_size) {
    const int*   col       = (const int*)d_in[0];
    const float* values    = (const float*)d_in[1];
    const float* adj       = (const float*)d_in[2];
    const int*   src_nodes = (const int*)d_in[3];
    const float* w1e = (const float*)d_in[4];
    const float* b1e = (const float*)d_in[5];
    const float* w2e = (const float*)d_in[6];
    const float* b2e = (const float*)d_in[7];
    const float* w1n = (const float*)d_in[8];
    const float* b1n = (const float*)d_in[9];
    const float* w2n = (const float*)d_in[10];
    const float* b2n = (const float*)d_in[11];
    float* out = (float*)d_out;

    const int nnz = in_sizes[0];   // 262144, divisible by 4
    const int E   = in_sizes[3];

    k_edge_node<<<GRID_ES, 512>>>(
        (const int4*)col, (const float4*)values,
        w1e, b1e, w2e, b2e, w1n, b1n, w2n, b2n, nnz / 4);
    k_row_score<<<GRID_RS, THREADS_RS>>>(adj, src_nodes, out, E);
}

// round 6
// speedup vs baseline: 1.4237x; 1.4237x over previous
#include <cuda_runtime.h>

#define N_NODES 8192
#define NV4 (N_NODES / 4)       // 2048 float4 per row
#define PSI 64

// __device__ scratch (no allocations allowed).
// g_agg zero-init at load; node_mlp reads-then-zeros it each replay.
__device__ float g_agg[N_NODES];
__device__ float g_t[N_NODES];
__device__ float g_s[N_NODES];

// ---------------------------------------------------------------------------
// Kernel 1: edge MLP + scatter-add by col.  4 edges per thread.
// ---------------------------------------------------------------------------
__global__ __launch_bounds__(256) void k_edge_scatter(
        const int4* __restrict__ col4,
        const float4* __restrict__ val4,
        const float* __restrict__ w1,
        const float* __restrict__ b1,
        const float* __restrict__ w2,
        const float* __restrict__ b2,
        int nnz4) {
    __shared__ float sw1[PSI], sb1[PSI], sw2[PSI], sb2;
    if (threadIdx.x < PSI) {
        sw1[threadIdx.x] = w1[threadIdx.x];
        sb1[threadIdx.x] = b1[threadIdx.x];
        sw2[threadIdx.x] = w2[threadIdx.x];
    }
    if (threadIdx.x == 0) sb2 = b2[0];
    __syncthreads();

    int i = blockIdx.x * blockDim.x + threadIdx.x;
    if (i >= nnz4) return;
    float4 v = val4[i];
    int4   c = col4[i];
    float a0 = sb2, a1 = sb2, a2 = sb2, a3 = sb2;
#pragma unroll
    for (int j = 0; j < PSI; j++) {
        float w = sw1[j], b = sb1[j], u = sw2[j];
        a0 = fmaf(fmaxf(fmaf(v.x, w, b), 0.0f), u, a0);
        a1 = fmaf(fmaxf(fmaf(v.y, w, b), 0.0f), u, a1);
        a2 = fmaf(fmaxf(fmaf(v.z, w, b), 0.0f), u, a2);
        a3 = fmaf(fmaxf(fmaf(v.w, w, b), 0.0f), u, a3);
    }
    atomicAdd(&g_agg[c.x], a0);
    atomicAdd(&g_agg[c.y], a1);
    atomicAdd(&g_agg[c.z], a2);
    atomicAdd(&g_agg[c.w], a3);
}

// ---------------------------------------------------------------------------
// Kernel 2: node MLP, store struct^2, re-zero g_agg for the next replay.
// ---------------------------------------------------------------------------
__global__ void k_node_mlp(const float* __restrict__ w1,
                           const float* __restrict__ b1,
                           const float* __restrict__ w2,
                           const float* __restrict__ b2) {
    __shared__ float sw1[PSI], sb1[PSI], sw2[PSI], sb2;
    if (threadIdx.x < PSI) {
        sw1[threadIdx.x] = w1[threadIdx.x];
        sb1[threadIdx.x] = b1[threadIdx.x];
        sw2[threadIdx.x] = w2[threadIdx.x];
    }
    if (threadIdx.x == 0) sb2 = b2[0];
    __syncthreads();

    int i = blockIdx.x * blockDim.x + threadIdx.x;
    if (i >= N_NODES) return;
    float x = g_agg[i];
    g_agg[i] = 0.0f;              // reset for next graph replay
    float acc = sb2;
#pragma unroll
    for (int j = 0; j < PSI; j++) {
        float h = fmaf(x, sw1[j], sb1[j]);
        acc = fmaf(fmaxf(h, 0.0f), sw2[j], acc);
    }
    g_t[i] = acc * acc;
}

// ---------------------------------------------------------------------------
// Kernel 3: row score.  s[r] = sum_n adj[r,n]^2 * t[n]
// 2 rows per 256-thread block, grid 4096.  No smem staging (t stays hot in
// L1), __ldcs streaming of adj, bounded unroll to keep regs ~40 and
// occupancy high.  This is the HBM-bound kernel: 256 MB read exactly once.
// ---------------------------------------------------------------------------
__global__ __launch_bounds__(256) void k_row_score(const float* __restrict__ adj) {
    const int row0 = blockIdx.x * 2;
    const float4* __restrict__ a0 =
        reinterpret_cast<const float4*>(adj + (size_t)row0 * N_NODES);
    const float4* __restrict__ a1 = a0 + NV4;
    const float4* __restrict__ tv = reinterpret_cast<const float4*>(g_t);

    float s0 = 0.0f, s1 = 0.0f;
#pragma unroll 2
    for (int i = threadIdx.x; i < NV4; i += 256) {
        float4 v0 = __ldcs(&a0[i]);
        float4 v1 = __ldcs(&a1[i]);
        float4 tw = __ldg(&tv[i]);
        s0 = fmaf(v0.x * v0.x, tw.x, s0);
        s0 = fmaf(v0.y * v0.y, tw.y, s0);
        s0 = fmaf(v0.z * v0.z, tw.z, s0);
        s0 = fmaf(v0.w * v0.w, tw.w, s0);
        s1 = fmaf(v1.x * v1.x, tw.x, s1);
        s1 = fmaf(v1.y * v1.y, tw.y, s1);
        s1 = fmaf(v1.z * v1.z, tw.z, s1);
        s1 = fmaf(v1.w * v1.w, tw.w, s1);
    }

    // warp reduction of both accumulators
#pragma unroll
    for (int off = 16; off > 0; off >>= 1) {
        s0 += __shfl_down_sync(0xffffffffu, s0, off);
        s1 += __shfl_down_sync(0xffffffffu, s1, off);
    }
    __shared__ float warp_sum[8][2];
    if ((threadIdx.x & 31) == 0) {
        warp_sum[threadIdx.x >> 5][0] = s0;
        warp_sum[threadIdx.x >> 5][1] = s1;
    }
    __syncthreads();
    if (threadIdx.x < 16) {
        float v = warp_sum[threadIdx.x & 7][threadIdx.x >> 3];
        v += __shfl_down_sync(0xffffu, v, 4, 8);
        v += __shfl_down_sync(0xffffu, v, 2, 8);
        v += __shfl_down_sync(0xffffu, v, 1, 8);
        if ((threadIdx.x & 7) == 0) g_s[row0 + (threadIdx.x >> 3)] = v;
    }
}

// ---------------------------------------------------------------------------
// Kernel 4: gather per-edge output
// ---------------------------------------------------------------------------
__global__ void k_gather(const int* __restrict__ src_nodes,
                         float* __restrict__ out, int E) {
    int e = blockIdx.x * blockDim.x + threadIdx.x;
    if (e < E) out[e] = g_s[src_nodes[e]];
}

// ---------------------------------------------------------------------------
// launch
// Inputs (metadata order): col, values, adj, src_nodes,
//                          w1e, b1e, w2e, b2e, w1n, b1n, w2n, b2n
// ---------------------------------------------------------------------------
extern "C" void kernel_launch(void* const* d_in, const int* in_sizes, int n_in,
                              void* d_out, int out_size) {
    const int*   col       = (const int*)d_in[0];
    const float* values    = (const float*)d_in[1];
    const float* adj       = (const float*)d_in[2];
    const int*   src_nodes = (const int*)d_in[3];
    const float* w1e = (const float*)d_in[4];
    const float* b1e = (const float*)d_in[5];
    const float* w2e = (const float*)d_in[6];
    const float* b2e = (const float*)d_in[7];
    const float* w1n = (const float*)d_in[8];
    const float* b1n = (const float*)d_in[9];
    const float* w2n = (const float*)d_in[10];
    const float* b2n = (const float*)d_in[11];
    float* out = (float*)d_out;

    const int nnz = in_sizes[0];   // 262144, divisible by 4
    const int E   = in_sizes[3];

    const int nnz4 = nnz / 4;
    k_edge_scatter<<<(nnz4 + 255) / 256, 256>>>(
        (const int4*)col, (const float4*)values, w1e, b1e, w2e, b2e, nnz4);
    k_node_mlp<<<(N_NODES + 255) / 256, 256>>>(w1n, b1n, w2n, b2n);
    k_row_score<<<N_NODES / 2, 256>>>(adj);
    k_gather<<<(E + 255) / 256, 256>>>(src_nodes, out, E);
}